// round 13
// baseline (speedup 1.0000x reference)
#include <cuda_runtime.h>

#define NQ      14
#define STATE   16384
#define BATCH   512
#define THREADS 512

typedef unsigned long long ull;

__device__ __forceinline__ int swz(int i) { return i ^ ((i >> 5) & 31); }

__device__ __forceinline__ float2 cmul(float2 a, float2 b) {
    return make_float2(a.x * b.x - a.y * b.y, a.x * b.y + a.y * b.x);
}

// ---- packed f32x2 (Blackwell FADD2/FMUL2 via PTX) ----
__device__ __forceinline__ ull pk(float x, float y) {
    ull r; asm("mov.b64 %0, {%1, %2};" : "=l"(r) : "f"(x), "f"(y)); return r;
}
__device__ __forceinline__ void upk(ull p, float& x, float& y) {
    asm("mov.b64 {%0, %1}, %2;" : "=f"(x), "=f"(y) : "l"(p));
}
__device__ __forceinline__ ull addx2(ull a, ull b) {
    ull r; asm("add.rn.f32x2 %0, %1, %2;" : "=l"(r) : "l"(a), "l"(b)); return r;
}
__device__ __forceinline__ ull subx2(ull a, ull b) {
    ull r; asm("sub.rn.f32x2 %0, %1, %2;" : "=l"(r) : "l"(a), "l"(b)); return r;
}
__device__ __forceinline__ ull mulx2(ull a, ull b) {
    ull r; asm("mul.rn.f32x2 %0, %1, %2;" : "=l"(r) : "l"(a), "l"(b)); return r;
}

// Packed butterflies: NE packs, NS stages over pack index bits.
template <int NE, int NS>
__device__ __forceinline__ void fwht_p(ull* v) {
#pragma unroll
    for (int s = 0; s < NS; s++) {
        const int h = 1 << s;
#pragma unroll
        for (int i = 0; i < NE / 2; i++) {
            const int k = i & (h - 1), g = (i >> s) << (s + 1);
            const int i0 = g + k, i1 = i0 + h;
            ull a = v[i0], b = v[i1];
            v[i0] = addx2(a, b);
            v[i1] = subx2(a, b);
        }
    }
}

// 32 reals packed as p[k] = (e_k, e_{k+16}): 5 stages (4 packed + cross-pack).
__device__ __forceinline__ void fwht32p(ull* p) {
    fwht_p<16, 4>(p);
#pragma unroll
    for (int k = 0; k < 16; k++) {
        float x, y; upk(p[k], x, y);
        p[k] = pk(x + y, x - y);
    }
}

// Dynamic smem: STATE floats data + fac(16 f2) + tabL(132 f2) + tabH(128 f2)
#define SMEM_BYTES (STATE * 4 + (16 + 132 + 128) * 8)

__global__ __launch_bounds__(THREADS, 2)
void rx_real(const float* __restrict__ pr, const float* __restrict__ pim,
             const float* __restrict__ th, float* __restrict__ out,
             long long ocap) {
    extern __shared__ float smf[];
    float2* fac  = (float2*)(smf + STATE);
    float2* tabL = fac + 16;     // entry m at [m + (m>>5)]
    float2* tabH = tabL + 132;

    const int b = blockIdx.x;
    const int t = threadIdx.x;

    if (t < NQ) {
        float s, c;
        __sincosf(-0.5f * th[b * NQ + t], &s, &c);
        fac[13 - t] = make_float2(c, s);    // bit p carries theta[13-p]
    }
    __syncthreads();
    // ev = e = tabH*tabL: e.x = cos(phase/2), e.y = -sin(phase/2). tabL has 2^-14.
    if (t < 256) {
        const int m    = t & 127;
        const int base = (t < 128) ? 0 : 7;
        float2 e = (t < 128) ? make_float2(0x1p-14f, 0.f) : make_float2(1.f, 0.f);
#pragma unroll
        for (int k = 0; k < 7; k++)
            if ((m >> k) & 1) e = cmul(e, fac[base + k]);
        if (t < 128) tabL[m + (m >> 5)] = e;
        else         tabH[m]            = e;
    }
    // (visibility of tables before pass C is covered by the A->B and B->C syncs)

    float* ob = out + (size_t)b * STATE;
    const long long rb = (long long)b * STATE;

#pragma unroll 1
    for (int part = 0; part < 2; part++) {
        const float* src = (part ? pim : pr) + (size_t)b * STATE;
        ull p[16];

        // ---- A: idx = t + 512j. FWHT bits 9..13 (cross-pack = bit 13).
#pragma unroll
        for (int k = 0; k < 16; k++)
            p[k] = pk(src[t + 512 * k], src[t + 512 * (k + 16)]);
        fwht32p(p);
#pragma unroll
        for (int k = 0; k < 16; k++) {
            float x, y; upk(p[k], x, y);
            smf[swz(t + 512 * k)]        = x;
            smf[swz(t + 512 * (k + 16))] = y;
        }
        __syncthreads();

        // ---- B: idx = (t>>4)*512 + (t&15) + 16j. FWHT bits 4..8.
        {
            const int base = (t >> 4) * 512 + (t & 15);
#pragma unroll
            for (int k = 0; k < 16; k++)
                p[k] = pk(smf[swz(base + 16 * k)], smf[swz(base + 16 * (k + 16))]);
            fwht32p(p);
#pragma unroll
            for (int k = 0; k < 16; k++) {
                float x, y; upk(p[k], x, y);
                smf[swz(base + 16 * k)]        = x;
                smf[swz(base + 16 * (k + 16))] = y;
            }
        }
        __syncthreads();

        // ---- C: idx = 32t + j. FWHT1 bits 0..3, coef multiply, FWHT2 bits 0..4.
        {
            const int base = 32 * t;
#pragma unroll
            for (int k = 0; k < 16; k++)
                p[k] = pk(smf[swz(base + k)], smf[swz(base + k + 16)]);
            fwht_p<16, 4>(p);                 // FWHT1 bits 0..3 (no cross-pack)

            const float2 hv = tabH[t >> 2];
            const int    lb = (t & 3) * 33;   // m0 + pad
#pragma unroll
            for (int k = 0; k < 16; k++) {
                const float2 e1 = cmul(hv, tabL[lb + k]);
                const float2 e2 = cmul(hv, tabL[lb + k + 16]);
                const float  c1 = part ? -e1.y : e1.x;   // S or C
                const float  c2 = part ? -e2.y : e2.x;
                p[k] = mulx2(p[k], pk(c1, c2));
            }
            fwht32p(p);                       // FWHT2 bits 0..4
#pragma unroll
            for (int k = 0; k < 16; k++) {
                float x, y; upk(p[k], x, y);
                smf[swz(base + k)]      = x;
                smf[swz(base + k + 16)] = y;
            }
        }
        __syncthreads();

        // ---- D: idx = (t>>5)*1024 + (t&31) + 32j. FWHT bits 5..9.
        {
            const int base = (t >> 5) * 1024 + (t & 31);
#pragma unroll
            for (int k = 0; k < 16; k++)
                p[k] = pk(smf[swz(base + 32 * k)], smf[swz(base + 32 * (k + 16))]);
            fwht32p(p);
#pragma unroll
            for (int k = 0; k < 16; k++) {
                float x, y; upk(p[k], x, y);
                smf[swz(base + 32 * k)]        = x;
                smf[swz(base + 32 * (k + 16))] = y;
            }
        }
        __syncthreads();

        // ---- E: idx = 1024j + t and +512. FWHT bits 10..13 (two 16-pt packed).
        {
#pragma unroll
            for (int j = 0; j < 16; j++)
                p[j] = pk(smf[swz(1024 * j + t)], smf[swz(1024 * j + t + 512)]);
            fwht_p<16, 4>(p);
            if (part == 0) {
#pragma unroll
                for (int j = 0; j < 16; j++) {
                    float x, y; upk(p[j], x, y);
                    if (rb + 1024 * j + t       < ocap) ob[1024 * j + t]       = x;
                    if (rb + 1024 * j + t + 512 < ocap) ob[1024 * j + t + 512] = y;
                }
            } else {
#pragma unroll
                for (int j = 0; j < 16; j++) {
                    float x, y; upk(p[j], x, y);
                    if (rb + 1024 * j + t < ocap)
                        ob[1024 * j + t] += x;
                    if (rb + 1024 * j + t + 512 < ocap)
                        ob[1024 * j + t + 512] += y;
                }
            }
        }
        __syncthreads();   // smem reuse by next part's pass A
    }
}

extern "C" void kernel_launch(void* const* d_in, const int* in_sizes, int n_in,
                              void* d_out, int out_size) {
    // Contract (established R8): fp32 planar inputs; output = fp32 REAL part.
    int ia = -1, ib = -1, ith = -1;
    for (int k = 0; k < n_in && ith < 0; k++) {
        const long long st = in_sizes[k];
        if (st <= 0 || (st * 8192) % 7) continue;
        const long long sp = st * 8192 / 7;
        int a = -1, bb = -1;
        for (int j = 0; j < n_in; j++) {
            if (j == k) continue;
            if ((long long)in_sizes[j] == sp) { if (a < 0) a = j; else if (bb < 0) bb = j; }
        }
        if (a >= 0 && bb >= 0) { ith = k; ia = a; ib = bb; }
    }
    if (ith < 0) { if (n_in < 3) return; ia = 0; ib = 1; ith = 2; }

    if (cudaFuncSetAttribute(rx_real,
            cudaFuncAttributeMaxDynamicSharedMemorySize, SMEM_BYTES) != cudaSuccess)
        return;
    rx_real<<<BATCH, THREADS, SMEM_BYTES>>>(
        (const float*)d_in[ia], (const float*)d_in[ib], (const float*)d_in[ith],
        (float*)d_out, (long long)out_size);
}

// round 14
// speedup vs baseline: 1.2643x; 1.2643x over previous
#include <cuda_runtime.h>

#define NQ      14
#define STATE   16384
#define BATCH   512
#define THREADS 512

typedef unsigned long long ull;

__device__ __forceinline__ int swz(int i) { return i ^ ((i >> 5) & 31); }

__device__ __forceinline__ float2 cmulh(float2 a, float2 b) {
    return make_float2(a.x * b.x - a.y * b.y, a.x * b.y + a.y * b.x);
}

// ---- packed f32x2 (Blackwell FADD2/FFMA2 via PTX) ----
__device__ __forceinline__ ull pk(float x, float y) {
    ull r; asm("mov.b64 %0, {%1, %2};" : "=l"(r) : "f"(x), "f"(y)); return r;
}
__device__ __forceinline__ void upk(ull p, float& x, float& y) {
    asm("mov.b64 {%0, %1}, %2;" : "=f"(x), "=f"(y) : "l"(p));
}
__device__ __forceinline__ ull addx2(ull a, ull b) {
    ull r; asm("add.rn.f32x2 %0, %1, %2;" : "=l"(r) : "l"(a), "l"(b)); return r;
}
__device__ __forceinline__ ull subx2(ull a, ull b) {
    ull r; asm("sub.rn.f32x2 %0, %1, %2;" : "=l"(r) : "l"(a), "l"(b)); return r;
}
__device__ __forceinline__ ull fma2(ull a, ull b, ull c) {
    ull r; asm("fma.rn.f32x2 %0, %1, %2, %3;" : "=l"(r) : "l"(a), "l"(b), "l"(c)); return r;
}

// Packed butterflies over register-index bits: NE packs, NS stages.
template <int NE, int NS>
__device__ __forceinline__ void fwht_p(ull* v) {
#pragma unroll
    for (int s = 0; s < NS; s++) {
        const int h = 1 << s;
#pragma unroll
        for (int i = 0; i < NE / 2; i++) {
            const int k = i & (h - 1), g = (i >> s) << (s + 1);
            const int i0 = g + k, i1 = i0 + h;
            ull a = v[i0], b = v[i1];
            v[i0] = addx2(a, b);
            v[i1] = subx2(a, b);
        }
    }
}

// One shuffle butterfly stage on 32 packed complex values, lane mask m.
__device__ __forceinline__ void shfl_stage_c(ull* v, int lane, int m) {
    const float sg = (lane & m) ? -1.f : 1.f;
    const ull   sp = pk(sg, sg);
#pragma unroll
    for (int j = 0; j < 32; j++) {
        float x, y; upk(v[j], x, y);
        const float ox = __shfl_xor_sync(0xFFFFFFFFu, x, m);
        const float oy = __shfl_xor_sync(0xFFFFFFFFu, y, m);
        v[j] = fma2(sp, v[j], pk(ox, oy));
    }
}

// SMEM: STATE ull data, then fac(16), tabL(132 padded), tabH(132 padded) as float2
#define SM_BYTES ((STATE + 16 + 132 + 132) * 8)

__global__ __launch_bounds__(THREADS, 1)
void rx_kron(const float* __restrict__ pr, const float* __restrict__ pim,
             const float* __restrict__ th, float* __restrict__ out,
             long long ocap) {
    extern __shared__ ull dat[];
    float*  smf  = (float*)dat;              // real-phase alias
    float2* fac  = (float2*)(dat + STATE);
    float2* tabL = fac + 16;                 // entry m at [m + (m>>5)], has 2^-14
    float2* tabH = tabL + 132;               // entry m at [m + (m>>5)]

    const int b    = blockIdx.x;
    const int t    = threadIdx.x;
    const int lane = t & 31;
    const int w    = t >> 5;
    const int l01  = lane & 3;
    const int l234 = lane >> 2;

    // ===== P1 global loads first (fire memory early). chunk=8w+l234, e=32*l01+r.
    ull v[32];
    {
        const float* pb = pr  + (size_t)b * STATE + (8 * w + l234) * 128 + 32 * l01;
        const float* qb = pim + (size_t)b * STATE + (8 * w + l234) * 128 + 32 * l01;
#pragma unroll
        for (int k = 0; k < 8; k++) {
            const float4 a = *(const float4*)(pb + 4 * k);
            const float4 c = *(const float4*)(qb + 4 * k);
            v[4 * k + 0] = pk(a.x, c.x);
            v[4 * k + 1] = pk(a.y, c.y);
            v[4 * k + 2] = pk(a.z, c.z);
            v[4 * k + 3] = pk(a.w, c.w);
        }
    }

    if (t < NQ) {
        float s, c;
        __sincosf(-0.5f * th[b * NQ + t], &s, &c);
        fac[13 - t] = make_float2(c, s);     // bit p carries theta[13-p]
    }
    __syncthreads();
    if (t < 256) {                            // Kronecker half-tables
        const int m    = t & 127;
        const int base = (t < 128) ? 0 : 7;
        float2 e = (t < 128) ? make_float2(0x1p-14f, 0.f) : make_float2(1.f, 0.f);
#pragma unroll
        for (int k = 0; k < 7; k++)
            if ((m >> k) & 1) e = cmulh(e, fac[base + k]);
        if (t < 128) tabL[m + (m >> 5)] = e;
        else         tabH[m + (m >> 5)] = e;
    }
    __syncthreads();

    // ===== P1: M_lo per chunk = FWHT_lo, ×tabL, FWHT_lo. e bits: r(0-4), l01(5-6).
    fwht_p<32, 5>(v);
    shfl_stage_c(v, lane, 1);
    shfl_stage_c(v, lane, 2);
    {
        const float2* tl = tabL + 33 * l01;   // padded base: e=32*l01+r -> 33*l01+r
#pragma unroll
        for (int r = 0; r < 32; r++) {
            const float2 e = tl[r];
            float x, y; upk(v[r], x, y);
            v[r] = pk(fmaf(x, e.x, -(y * e.y)), fmaf(x, e.y, y * e.x));
        }
    }
    fwht_p<32, 5>(v);
    shfl_stage_c(v, lane, 1);
    shfl_stage_c(v, lane, 2);
    {
        const int ib = 1024 * w + 128 * l234 + 32 * l01;
#pragma unroll
        for (int r = 0; r < 32; r++) dat[swz(ib + r)] = v[r];
    }
    __syncthreads();

    // ===== P2: M_hi per comb. hi = 4s + l01 (s reg bits 2-6, l01 bits 0-1),
    //           lo = w + 16*l234. i = 512 s + 128*l01 + lo.
    const int ib2 = 128 * l01 + w + 16 * l234;
#pragma unroll
    for (int s = 0; s < 32; s++) v[s] = dat[swz(ib2 + 512 * s)];
    __syncthreads();                          // all complex reads done before writes

    fwht_p<32, 5>(v);                         // hi bits 2..6
    shfl_stage_c(v, lane, 1);                 // hi bits 0..1
    shfl_stage_c(v, lane, 2);

    float rr[32];
#pragma unroll
    for (int s = 0; s < 32; s++) {            // ×tabH, take real part
        const int h = 4 * s + l01;
        const float2 e = tabH[h + (h >> 5)];
        float x, y; upk(v[s], x, y);
        rr[s] = fmaf(x, e.x, -(y * e.y));
    }
    // real FWHT over hi: shuffle bits 0-1, then reg bits 2-6 (packed pairs k,k+16)
#pragma unroll
    for (int m = 1; m <= 2; m <<= 1) {
        const float sg = (lane & m) ? -1.f : 1.f;
#pragma unroll
        for (int s = 0; s < 32; s++)
            rr[s] = fmaf(sg, rr[s], __shfl_xor_sync(0xFFFFFFFFu, rr[s], m));
    }
    {
        ull p[16];
#pragma unroll
        for (int k = 0; k < 16; k++) p[k] = pk(rr[k], rr[k + 16]);
        fwht_p<16, 4>(p);                     // strides 1,2,4,8 over s
#pragma unroll
        for (int k = 0; k < 16; k++) {        // stride 16: within-pack butterfly
            float x, y; upk(p[k], x, y);
            smf[swz(ib2 + 512 * k)]        = x + y;
            smf[swz(ib2 + 512 * (k + 16))] = x - y;
        }
    }
    __syncthreads();

    // ===== P3: coalesced copy real plane to global. i = 4t + j + 2048*j2.
    {
        float* ob = out + (size_t)b * STATE;
        const long long rb = (long long)b * STATE;
        const int q = (t >> 3) & 3;           // XOR permutation within 16B quad
#pragma unroll
        for (int j2 = 0; j2 < 8; j2++) {
            const int i0 = 4 * t + 2048 * j2;
            const int ph = swz(i0) & ~3;      // aligned quad base (swz low2 = q)
            const float4 raw = *(const float4*)(smf + ph);
            const float* rp = (const float*)&raw;
            if (rb + i0 + 3 < ocap) {
                float4 ov;
                ov.x = rp[0 ^ q]; ov.y = rp[1 ^ q];
                ov.z = rp[2 ^ q]; ov.w = rp[3 ^ q];
                *(float4*)(ob + i0) = ov;
            } else {
#pragma unroll
                for (int j = 0; j < 4; j++)
                    if (rb + i0 + j < ocap) ob[i0 + j] = rp[j ^ q];
            }
        }
    }
}

extern "C" void kernel_launch(void* const* d_in, const int* in_sizes, int n_in,
                              void* d_out, int out_size) {
    // Contract (established R8): fp32 planar inputs; output = fp32 REAL part.
    int ia = -1, ib = -1, ith = -1;
    for (int k = 0; k < n_in && ith < 0; k++) {
        const long long st = in_sizes[k];
        if (st <= 0 || (st * 8192) % 7) continue;
        const long long sp = st * 8192 / 7;
        int a = -1, bb = -1;
        for (int j = 0; j < n_in; j++) {
            if (j == k) continue;
            if ((long long)in_sizes[j] == sp) { if (a < 0) a = j; else if (bb < 0) bb = j; }
        }
        if (a >= 0 && bb >= 0) { ith = k; ia = a; ib = bb; }
    }
    if (ith < 0) { if (n_in < 3) return; ia = 0; ib = 1; ith = 2; }

    if (cudaFuncSetAttribute(rx_kron,
            cudaFuncAttributeMaxDynamicSharedMemorySize, SM_BYTES) != cudaSuccess)
        return;
    rx_kron<<<BATCH, THREADS, SM_BYTES>>>(
        (const float*)d_in[ia], (const float*)d_in[ib], (const float*)d_in[ith],
        (float*)d_out, (long long)out_size);
}

// round 16
// speedup vs baseline: 1.8198x; 1.4394x over previous
#include <cuda_runtime.h>

#define NQ      14
#define STATE   16384
#define BATCH   512
#define THREADS 512

typedef unsigned long long ull;

__device__ __forceinline__ int swz(int i) { return i ^ ((i >> 5) & 31); }

__device__ __forceinline__ float2 cmulh(float2 a, float2 b) {
    return make_float2(a.x * b.x - a.y * b.y, a.x * b.y + a.y * b.x);
}

// ---- packed f32x2 (Blackwell FADD2 via PTX) ----
__device__ __forceinline__ ull pk(float x, float y) {
    ull r; asm("mov.b64 %0, {%1, %2};" : "=l"(r) : "f"(x), "f"(y)); return r;
}
__device__ __forceinline__ void upk(ull p, float& x, float& y) {
    asm("mov.b64 {%0, %1}, %2;" : "=f"(x), "=f"(y) : "l"(p));
}
__device__ __forceinline__ ull addx2(ull a, ull b) {
    ull r; asm("add.rn.f32x2 %0, %1, %2;" : "=l"(r) : "l"(a), "l"(b)); return r;
}
__device__ __forceinline__ ull subx2(ull a, ull b) {
    ull r; asm("sub.rn.f32x2 %0, %1, %2;" : "=l"(r) : "l"(a), "l"(b)); return r;
}

// Packed butterflies over register-index bits: NE packs, NS stages.
template <int NE, int NS>
__device__ __forceinline__ void fwht_p(ull* v) {
#pragma unroll
    for (int s = 0; s < NS; s++) {
        const int h = 1 << s;
#pragma unroll
        for (int i = 0; i < NE / 2; i++) {
            const int k = i & (h - 1), g = (i >> s) << (s + 1);
            const int i0 = g + k, i1 = i0 + h;
            ull a = v[i0], b = v[i1];
            v[i0] = addx2(a, b);
            v[i1] = subx2(a, b);
        }
    }
}

// 32 reals packed as p[k] = (e_k, e_{k+16}): stages 1,2,4,8 packed + cross-pack 16.
__device__ __forceinline__ void fwht32p(ull* p) {
    fwht_p<16, 4>(p);
#pragma unroll
    for (int k = 0; k < 16; k++) {
        float x, y; upk(p[k], x, y);
        p[k] = pk(x + y, x - y);
    }
}

// SMEM: complex ull[STATE] | real float[STATE] | fac(16 f2) tabL(132 f2) tabH(128 f2)
#define SM_BYTES (STATE * 8 + STATE * 4 + (16 + 132 + 128) * 8)

__global__ __launch_bounds__(THREADS, 1)
void rx_fused(const float* __restrict__ pr, const float* __restrict__ pim,
              const float* __restrict__ th, float* __restrict__ out,
              long long ocap) {
    extern __shared__ ull dat[];                    // complex plane, 128 KB
    float*  smr  = (float*)(dat + STATE);           // real plane, 64 KB
    float2* fac  = (float2*)(smr + STATE);
    float2* tabL = fac + 16;                        // entry m at [m + (m>>5)]
    float2* tabH = tabL + 132;

    const int b = blockIdx.x;
    const int t = threadIdx.x;

    if (t < NQ) {
        float s, c;
        __sincosf(-0.5f * th[b * NQ + t], &s, &c);
        fac[13 - t] = make_float2(c, s);            // bit p carries theta[13-p]
    }

    // ===== Pass A: FWHT1 bits 9..13 (packed complex); store complex smem.
    ull v[32];
    {
        const float* prb = pr  + (size_t)b * STATE;
        const float* pib = pim + (size_t)b * STATE;
#pragma unroll
        for (int j = 0; j < 32; j++)
            v[j] = pk(prb[t + 512 * j], pib[t + 512 * j]);
    }
    fwht_p<32, 5>(v);
#pragma unroll
    for (int j = 0; j < 32; j++) dat[swz(t + 512 * j)] = v[j];
    __syncthreads();                                 // S1: covers fac + pass A

    // Kronecker half-tables, built inside pass-B's epoch (warps 0-7 only).
    // ev[s] = tabH[s>>7] * tabL[s&127]; tabL carries 2^-14.
    if (t < 256) {
        const int m    = t & 127;
        const int base = (t < 128) ? 0 : 7;
        float2 e = (t < 128) ? make_float2(0x1p-14f, 0.f) : make_float2(1.f, 0.f);
#pragma unroll
        for (int k = 0; k < 7; k++)
            if ((m >> k) & 1) e = cmulh(e, fac[base + k]);
        if (t < 128) tabL[m + (m >> 5)] = e;
        else         tabH[m]            = e;
    }

    // ===== Pass B: FWHT1 bits 4..8 (packed complex).
    {
        const int base = (t >> 4) * 512 + (t & 15);
#pragma unroll
        for (int j = 0; j < 32; j++) v[j] = dat[swz(base + 16 * j)];
        fwht_p<32, 5>(v);
#pragma unroll
        for (int j = 0; j < 32; j++) dat[swz(base + 16 * j)] = v[j];
    }
    __syncthreads();                                 // S2: covers tables + pass B

    // ===== Pass C: FWHT1 bits 0..3, diag -> REAL, FWHT2 bits 0..4.
    //       (scalar swz accesses — verified pattern from R9/R11)
    {
        const int base = 32 * t;
#pragma unroll
        for (int j = 0; j < 32; j++) v[j] = dat[swz(base + j)];
        fwht_p<32, 4>(v);                            // FWHT1 bits 0..3

        const float2  hv = tabH[t >> 2];
        const float2* tl = tabL + (t & 3) * 33;      // padded base
        float r[32];
#pragma unroll
        for (int j = 0; j < 32; j++) {
            const float2 e = cmulh(hv, tl[j]);
            float x, y; upk(v[j], x, y);
            r[j] = fmaf(x, e.x, -(y * e.y));         // Re(ev * w)
        }

        ull p[16];
#pragma unroll
        for (int k = 0; k < 16; k++) p[k] = pk(r[k], r[k + 16]);
        fwht32p(p);                                  // FWHT2 bits 0..4
#pragma unroll
        for (int k = 0; k < 16; k++) {
            float x, y; upk(p[k], x, y);
            smr[swz(base + k)]      = x;             // separate region: no alias
            smr[swz(base + k + 16)] = y;             // barrier needed
        }
    }
    __syncthreads();                                 // S3

    // ===== Pass D: FWHT2 bits 5..9 (packed real).
    {
        const int base = (t >> 5) * 1024 + (t & 31);
        ull p[16];
#pragma unroll
        for (int k = 0; k < 16; k++)
            p[k] = pk(smr[swz(base + 32 * k)], smr[swz(base + 32 * (k + 16))]);
        fwht32p(p);
#pragma unroll
        for (int k = 0; k < 16; k++) {
            float x, y; upk(p[k], x, y);
            smr[swz(base + 32 * k)]        = x;
            smr[swz(base + 32 * (k + 16))] = y;
        }
    }
    __syncthreads();                                 // S4

    // ===== Pass E: FWHT2 bits 10..13 (two 16-pt transforms packed); write out.
    {
        float* ob = out + (size_t)b * STATE;
        const long long rb = (long long)b * STATE;
        ull p[16];
#pragma unroll
        for (int j = 0; j < 16; j++)
            p[j] = pk(smr[swz(1024 * j + t)], smr[swz(1024 * j + t + 512)]);
        fwht_p<16, 4>(p);
#pragma unroll
        for (int j = 0; j < 16; j++) {
            float x, y; upk(p[j], x, y);
            if (rb + 1024 * j + t       < ocap) ob[1024 * j + t]       = x;
            if (rb + 1024 * j + t + 512 < ocap) ob[1024 * j + t + 512] = y;
        }
    }
}

extern "C" void kernel_launch(void* const* d_in, const int* in_sizes, int n_in,
                              void* d_out, int out_size) {
    // Contract (established R8): fp32 planar inputs; output = fp32 REAL part.
    int ia = -1, ib = -1, ith = -1;
    for (int k = 0; k < n_in && ith < 0; k++) {
        const long long st = in_sizes[k];
        if (st <= 0 || (st * 8192) % 7) continue;
        const long long sp = st * 8192 / 7;
        int a = -1, bb = -1;
        for (int j = 0; j < n_in; j++) {
            if (j == k) continue;
            if ((long long)in_sizes[j] == sp) { if (a < 0) a = j; else if (bb < 0) bb = j; }
        }
        if (a >= 0 && bb >= 0) { ith = k; ia = a; ib = bb; }
    }
    if (ith < 0) { if (n_in < 3) return; ia = 0; ib = 1; ith = 2; }

    if (cudaFuncSetAttribute(rx_fused,
            cudaFuncAttributeMaxDynamicSharedMemorySize, SM_BYTES) != cudaSuccess)
        return;
    rx_fused<<<BATCH, THREADS, SM_BYTES>>>(
        (const float*)d_in[ia], (const float*)d_in[ib], (const float*)d_in[ith],
        (float*)d_out, (long long)out_size);
}

// round 17
// speedup vs baseline: 2.1495x; 1.1812x over previous
#include <cuda_runtime.h>

#define NQ      14
#define STATE   16384
#define BATCH   512
#define THREADS 512
#define RPC     4        // rows per CTA
#define GRID    (BATCH / RPC)

typedef unsigned long long ull;

__device__ __forceinline__ int swz(int i) { return i ^ ((i >> 5) & 31); }

__device__ __forceinline__ float2 cmulh(float2 a, float2 b) {
    return make_float2(a.x * b.x - a.y * b.y, a.x * b.y + a.y * b.x);
}

// ---- packed f32x2 (Blackwell FADD2 via PTX) ----
__device__ __forceinline__ ull pk(float x, float y) {
    ull r; asm("mov.b64 %0, {%1, %2};" : "=l"(r) : "f"(x), "f"(y)); return r;
}
__device__ __forceinline__ void upk(ull p, float& x, float& y) {
    asm("mov.b64 {%0, %1}, %2;" : "=f"(x), "=f"(y) : "l"(p));
}
__device__ __forceinline__ ull addx2(ull a, ull b) {
    ull r; asm("add.rn.f32x2 %0, %1, %2;" : "=l"(r) : "l"(a), "l"(b)); return r;
}
__device__ __forceinline__ ull subx2(ull a, ull b) {
    ull r; asm("sub.rn.f32x2 %0, %1, %2;" : "=l"(r) : "l"(a), "l"(b)); return r;
}

template <int NE, int NS>
__device__ __forceinline__ void fwht_p(ull* v) {
#pragma unroll
    for (int s = 0; s < NS; s++) {
        const int h = 1 << s;
#pragma unroll
        for (int i = 0; i < NE / 2; i++) {
            const int k = i & (h - 1), g = (i >> s) << (s + 1);
            const int i0 = g + k, i1 = i0 + h;
            ull a = v[i0], b = v[i1];
            v[i0] = addx2(a, b);
            v[i1] = subx2(a, b);
        }
    }
}

// 32 reals packed as p[k] = (e_k, e_{k+16}): stages 1,2,4,8 packed + cross-pack 16.
__device__ __forceinline__ void fwht32p(ull* p) {
    fwht_p<16, 4>(p);
#pragma unroll
    for (int k = 0; k < 16; k++) {
        float x, y; upk(p[k], x, y);
        p[k] = pk(x + y, x - y);
    }
}

// ---- cp.async helpers ----
__device__ __forceinline__ void cp16(unsigned dst, const void* src) {
    asm volatile("cp.async.cg.shared.global [%0], [%1], 16;"
                 :: "r"(dst), "l"(src) : "memory");
}
// Stage one row: pr -> dat bytes [0,64K), pim -> [64K,128K), linear float4s.
__device__ __forceinline__ void prefetch_row(unsigned smb, const float* prb,
                                             const float* pib, int t) {
#pragma unroll
    for (int k = 0; k < 8; k++) {
        const int q = t + 512 * k;                    // float4 index, < 4096
        cp16(smb + q * 16,         (const float4*)prb + q);
        cp16(smb + 65536 + q * 16, (const float4*)pib + q);
    }
    asm volatile("cp.async.commit_group;" ::: "memory");
}

// SMEM: complex ull[STATE] (also raw staging) | real float[STATE] | tables
#define SM_BYTES (STATE * 8 + STATE * 4 + (16 + 132 + 128) * 8)

__global__ __launch_bounds__(THREADS, 1)
void rx_fused(const float* __restrict__ pr, const float* __restrict__ pim,
              const float* __restrict__ th, float* __restrict__ out,
              long long ocap) {
    extern __shared__ ull dat[];                    // complex plane / staging, 128 KB
    float*  smr  = (float*)(dat + STATE);           // real plane, 64 KB
    float2* fac  = (float2*)(smr + STATE);
    float2* tabL = fac + 16;                        // entry m at [m + (m>>5)]
    float2* tabH = tabL + 132;
    const float* df = (const float*)dat;            // raw staging view

    const int t   = threadIdx.x;
    const unsigned smb = (unsigned)__cvta_generic_to_shared(dat);

    // Prefetch first row.
    prefetch_row(smb, pr + (size_t)(RPC * blockIdx.x) * STATE,
                      pim + (size_t)(RPC * blockIdx.x) * STATE, t);

#pragma unroll 1
    for (int r = 0; r < RPC; r++) {
        const int b = RPC * blockIdx.x + r;

        asm volatile("cp.async.wait_group 0;" ::: "memory");
        __syncthreads();                             // S0: staging ready, prev E done

        if (t < NQ) {
            float s, c;
            __sincosf(-0.5f * th[b * NQ + t], &s, &c);
            fac[13 - t] = make_float2(c, s);         // bit p carries theta[13-p]
        }

        // ===== Pass A: read raw from staging, FWHT1 bits 9..13, write packed.
        ull v[32];
#pragma unroll
        for (int j = 0; j < 32; j++) {
            const int idx = t + 512 * j;
            v[j] = pk(df[idx], df[16384 + idx]);
        }
        fwht_p<32, 5>(v);
        __syncthreads();                             // S0b: all raw reads done
#pragma unroll
        for (int j = 0; j < 32; j++) dat[swz(t + 512 * j)] = v[j];
        __syncthreads();                             // S1

        // Kronecker half-tables (inside B's epoch). tabL carries 2^-14.
        if (t < 256) {
            const int m    = t & 127;
            const int base = (t < 128) ? 0 : 7;
            float2 e = (t < 128) ? make_float2(0x1p-14f, 0.f)
                                 : make_float2(1.f, 0.f);
#pragma unroll
            for (int k = 0; k < 7; k++)
                if ((m >> k) & 1) e = cmulh(e, fac[base + k]);
            if (t < 128) tabL[m + (m >> 5)] = e;
            else         tabH[m]            = e;
        }

        // ===== Pass B: FWHT1 bits 4..8.
        {
            const int base = (t >> 4) * 512 + (t & 15);
#pragma unroll
            for (int j = 0; j < 32; j++) v[j] = dat[swz(base + 16 * j)];
            fwht_p<32, 5>(v);
#pragma unroll
            for (int j = 0; j < 32; j++) dat[swz(base + 16 * j)] = v[j];
        }
        __syncthreads();                             // S2

        // ===== Pass C: FWHT1 bits 0..3, diag -> REAL, FWHT2 bits 0..4.
        {
            const int base = 32 * t;
#pragma unroll
            for (int j = 0; j < 32; j++) v[j] = dat[swz(base + j)];
            fwht_p<32, 4>(v);

            const float2  hv = tabH[t >> 2];
            const float2* tl = tabL + (t & 3) * 33;
            float rr[32];
#pragma unroll
            for (int j = 0; j < 32; j++) {
                const float2 e = cmulh(hv, tl[j]);
                float x, y; upk(v[j], x, y);
                rr[j] = fmaf(x, e.x, -(y * e.y));    // Re(ev * w)
            }
            ull p[16];
#pragma unroll
            for (int k = 0; k < 16; k++) p[k] = pk(rr[k], rr[k + 16]);
            fwht32p(p);
#pragma unroll
            for (int k = 0; k < 16; k++) {
                float x, y; upk(p[k], x, y);
                smr[swz(base + k)]      = x;
                smr[swz(base + k + 16)] = y;
            }
        }
        __syncthreads();                             // S3: dat is now dead

        // Prefetch next row into dat while D/E run on smr.
        if (r + 1 < RPC)
            prefetch_row(smb, pr + (size_t)(b + 1) * STATE,
                              pim + (size_t)(b + 1) * STATE, t);

        // ===== Pass D: FWHT2 bits 5..9.
        {
            const int base = (t >> 5) * 1024 + (t & 31);
            ull p[16];
#pragma unroll
            for (int k = 0; k < 16; k++)
                p[k] = pk(smr[swz(base + 32 * k)], smr[swz(base + 32 * (k + 16))]);
            fwht32p(p);
#pragma unroll
            for (int k = 0; k < 16; k++) {
                float x, y; upk(p[k], x, y);
                smr[swz(base + 32 * k)]        = x;
                smr[swz(base + 32 * (k + 16))] = y;
            }
        }
        __syncthreads();                             // S4

        // ===== Pass E: FWHT2 bits 10..13; write real plane to global.
        {
            float* ob = out + (size_t)b * STATE;
            const long long rb = (long long)b * STATE;
            ull p[16];
#pragma unroll
            for (int j = 0; j < 16; j++)
                p[j] = pk(smr[swz(1024 * j + t)], smr[swz(1024 * j + t + 512)]);
            fwht_p<16, 4>(p);
#pragma unroll
            for (int j = 0; j < 16; j++) {
                float x, y; upk(p[j], x, y);
                if (rb + 1024 * j + t       < ocap) ob[1024 * j + t]       = x;
                if (rb + 1024 * j + t + 512 < ocap) ob[1024 * j + t + 512] = y;
            }
        }
    }
}

extern "C" void kernel_launch(void* const* d_in, const int* in_sizes, int n_in,
                              void* d_out, int out_size) {
    // Contract (established R8): fp32 planar inputs; output = fp32 REAL part.
    int ia = -1, ib = -1, ith = -1;
    for (int k = 0; k < n_in && ith < 0; k++) {
        const long long st = in_sizes[k];
        if (st <= 0 || (st * 8192) % 7) continue;
        const long long sp = st * 8192 / 7;
        int a = -1, bb = -1;
        for (int j = 0; j < n_in; j++) {
            if (j == k) continue;
            if ((long long)in_sizes[j] == sp) { if (a < 0) a = j; else if (bb < 0) bb = j; }
        }
        if (a >= 0 && bb >= 0) { ith = k; ia = a; ib = bb; }
    }
    if (ith < 0) { if (n_in < 3) return; ia = 0; ib = 1; ith = 2; }

    if (cudaFuncSetAttribute(rx_fused,
            cudaFuncAttributeMaxDynamicSharedMemorySize, SM_BYTES) != cudaSuccess)
        return;
    rx_fused<<<GRID, THREADS, SM_BYTES>>>(
        (const float*)d_in[ia], (const float*)d_in[ib], (const float*)d_in[ith],
        (float*)d_out, (long long)out_size);
}